// round 14
// baseline (speedup 1.0000x reference)
#include <cuda_runtime.h>
#include <cuda_fp16.h>
#include <math.h>
#include <stdint.h>

#define L_LAYERS 250
#define N_TRACES 600
#define N_THETA  30
#define NI   249                 // interfaces (ref row 249 is zero)
#define NCOL 18000
#define NBLK 141                 // ceil(18000/128) n-tiles, one block each

// smem layout (halves): A 256x264, B 256x136, then 64 floats sincos
#define APITCH 264
#define BPITCH 136
#define A_HALVES (256 * APITCH)      // 67584
#define B_HALVES (256 * BPITCH)      // 34816
#define SMEM_BYTES ((A_HALVES + B_HALVES) * 2 + 256)   // 205056

__device__ __forceinline__ float sqrt_approx(float x) {
    float r;
    asm("sqrt.approx.f32 %0, %1;" : "=f"(r) : "f"(x));
    return r;
}
__device__ __forceinline__ uint32_t smaddr(const void* p) {
    return (uint32_t)__cvta_generic_to_shared(p);
}
__device__ __forceinline__ void ldsm4(uint32_t a[4], uint32_t addr) {
    asm volatile("ldmatrix.sync.aligned.m8n8.x4.shared.b16 {%0,%1,%2,%3}, [%4];"
                 : "=r"(a[0]), "=r"(a[1]), "=r"(a[2]), "=r"(a[3]) : "r"(addr));
}
__device__ __forceinline__ void ldsm4t(uint32_t a[4], uint32_t addr) {
    asm volatile("ldmatrix.sync.aligned.m8n8.x4.trans.shared.b16 {%0,%1,%2,%3}, [%4];"
                 : "=r"(a[0]), "=r"(a[1]), "=r"(a[2]), "=r"(a[3]) : "r"(addr));
}
__device__ __forceinline__ void mma16816(float c[4], const uint32_t a[4], const uint32_t b[2]) {
    asm volatile("mma.sync.aligned.m16n8k16.row.col.f32.f16.f16.f32 "
                 "{%0,%1,%2,%3}, {%4,%5,%6,%7}, {%8,%9}, {%0,%1,%2,%3};"
                 : "+f"(c[0]), "+f"(c[1]), "+f"(c[2]), "+f"(c[3])
                 : "r"(a[0]), "r"(a[1]), "r"(a[2]), "r"(a[3]), "r"(b[0]), "r"(b[1]));
}

// ---------------------------------------------------------------------------
// ONE kernel, one wave (141 blocks, 1 block/SM).
// Per block (n-tile bn..bn+127):
//  1. convert full W (fp32 -> fp16) into smem A [256 x 256, pitch 264]
//  2. compute Zoeppritz Rpp (Aki & Richards closed form, exact for these
//     input ranges) for its 128 n-columns x 249 interfaces into smem B
//     [256 k x 128 n, pitch 136]
//  3. __syncthreads once, then barrier-free HMMA GEMM (2 m-passes of
//     128x128, fully unrolled 16 k-steps, operands fully smem-resident)
// ---------------------------------------------------------------------------
__global__ __launch_bounds__(256, 1)
void zoe_all(const float* __restrict__ vp,
             const float* __restrict__ vs,
             const float* __restrict__ rho,
             const float* __restrict__ theta,
             const float* __restrict__ W,
             float* __restrict__ out) {
    extern __shared__ __half sm[];
    __half* As = sm;                        // A_HALVES
    __half* Bs = sm + A_HALVES;             // B_HALVES
    float*  s_sc = (float*)(Bs + B_HALVES); // [0..29] sin, [32..61] cos

    int tid = threadIdx.x;
    int bn  = blockIdx.x * 128;

    // ---- sincos table ----
    if (tid < N_THETA) {
        float sv, cv;
        sincosf(theta[tid], &sv, &cv);
        s_sc[tid] = sv;
        s_sc[32 + tid] = cv;
    }

    // ---- B zero-fill (covers pad rows k>=249 and pad cols n>=18000) ----
    {
        uint4 z = make_uint4(0, 0, 0, 0);
        uint4* b4 = (uint4*)Bs;
        const int NV = B_HALVES * 2 / 16;   // 4352
#pragma unroll
        for (int i = 0; i < NV / 256; i++)
            b4[tid + i * 256] = z;
    }

    // ---- A convert: W fp32 -> fp16 (pads -> 0) ----
    // i = m*256 + k; warp lanes get consecutive k -> coalesced LDG.
#pragma unroll 4
    for (int i = tid; i < 256 * 256; i += 256) {
        int m = i >> 8, k = i & 255;
        float v = (m < L_LAYERS && k < L_LAYERS) ? W[m * L_LAYERS + k] : 0.f;
        As[m * APITCH + k] = __float2half(v);
    }
    __syncthreads();   // sincos ready for phase1

    // ---- Phase 1: Zoeppritz into B (249 x 128 items) ----
    for (int i = tid; i < NI * 128; i += 256) {
        int l  = i >> 7;
        int nl = i & 127;
        int n  = bn + nl;
        if (n >= NCOL) continue;
        int t = n / N_THETA;
        int a = n - t * N_THETA;

        float a1 = vp[l * N_TRACES + t],  a2 = vp[(l + 1) * N_TRACES + t];
        float b1 = vs[l * N_TRACES + t],  b2 = vs[(l + 1) * N_TRACES + t];
        float r1 = rho[l * N_TRACES + t], r2 = rho[(l + 1) * N_TRACES + t];

        float sth = s_sc[a], cth = s_sc[32 + a];
        float p  = __fdividef(sth, a1);
        float p2 = p * p;

        float st2 = p * a2;
        float ct2 = sqrt_approx(fmaxf(1.f - st2 * st2, 0.f));
        float sp1 = p * b1;
        float cp1 = sqrt_approx(fmaxf(1.f - sp1 * sp1, 0.f));
        float sp2 = p * b2;
        float cp2 = sqrt_approx(fmaxf(1.f - sp2 * sp2, 0.f));

        float d  = 2.f * r2 * (b2 * b2) - 2.f * r1 * (b1 * b1);
        float dp2 = d * p2;
        float A = (r2 - r1) - dp2;
        float B = r2 - dp2;
        float C = r1 + dp2;

        float X = B * cth * a2;
        float Y = C * ct2 * a1;
        float E = X + Y;
        float F = fmaf(B * cp1, b2, C * cp2 * b1);
        float Z = d * cth * cp2;
        float Aa1b2 = A * a1 * b2;
        float G = Aa1b2 - Z;
        float H = fmaf(-d * ct2, cp1, A * a2 * b1);
        float D = fmaf(E, F, G * H * p2);
        float num = fmaf(X - Y, F, -(Aa1b2 + Z) * H * p2);

        Bs[l * BPITCH + nl] = __float2half(__fdividef(num, D));
    }
    __syncthreads();   // operands fully resident; the LAST barrier

    // ---- Phase 2: GEMM, 2 m-passes of 128x128, barrier-free ----
    int wid = tid >> 5, lane = tid & 31;
    int wm = (wid >> 1) * 32;                  // 0,32,64,96
    int wn = (wid & 1) * 64;                   // 0 or 64
    int r8 = lane >> 3, i8 = lane & 7;
    int a_frow = wm + (r8 & 1) * 8 + i8;       // + mt*16 (+ pass*128)
    int a_fcol = (r8 >> 1) * 8;                // + ks*16
    int b_fkrow = (r8 & 1) * 8 + i8;           // + ks*16
    int b_fncol = wn + (r8 >> 1) * 8;          // + pair*16

    uint32_t sAf = smaddr(&As[a_frow * APITCH + a_fcol]);
    uint32_t sBf = smaddr(&Bs[b_fkrow * BPITCH + b_fncol]);

#pragma unroll
    for (int pass = 0; pass < 2; pass++) {
        float acc[2][8][4];
#pragma unroll
        for (int mt = 0; mt < 2; mt++)
#pragma unroll
            for (int nt = 0; nt < 8; nt++)
#pragma unroll
                for (int e = 0; e < 4; e++) acc[mt][nt][e] = 0.f;

        uint32_t aBase = sAf + pass * 128 * (APITCH * 2);

#pragma unroll
        for (int ks = 0; ks < 16; ks++) {
            uint32_t bhf[8][2];
#pragma unroll
            for (int pair = 0; pair < 4; pair++) {
                uint32_t t4[4];
                ldsm4t(t4, sBf + ks * 16 * (BPITCH * 2) + pair * 32);
                bhf[pair * 2][0] = t4[0]; bhf[pair * 2][1] = t4[1];
                bhf[pair * 2 + 1][0] = t4[2]; bhf[pair * 2 + 1][1] = t4[3];
            }
#pragma unroll
            for (int mt = 0; mt < 2; mt++) {
                uint32_t ahf[4];
                ldsm4(ahf, aBase + mt * 16 * (APITCH * 2) + ks * 32);
#pragma unroll
                for (int nt = 0; nt < 8; nt++) {
                    mma16816(acc[mt][nt], ahf, bhf[nt]);
                }
            }
        }

        // epilogue for this pass
        int bm = pass * 128;
#pragma unroll
        for (int mt = 0; mt < 2; mt++) {
#pragma unroll
            for (int nt = 0; nt < 8; nt++) {
                int l0 = bm + wm + mt * 16 + (lane >> 2);
                int n0 = bn + wn + nt * 8 + (lane & 3) * 2;
#pragma unroll
                for (int e = 0; e < 4; e++) {
                    int l = l0 + (e >> 1) * 8;
                    int n = n0 + (e & 1);
                    if (l < L_LAYERS && n < NCOL) {
                        int t = n / N_THETA;
                        int a = n - t * N_THETA;
                        out[t * (L_LAYERS * N_THETA) + l * N_THETA + a] =
                            acc[mt][nt][e];
                    }
                }
            }
        }
    }
}

extern "C" void kernel_launch(void* const* d_in, const int* in_sizes, int n_in,
                              void* d_out, int out_size) {
    const float* vp      = (const float*)d_in[0];
    const float* vs      = (const float*)d_in[1];
    const float* rho     = (const float*)d_in[2];
    const float* theta   = (const float*)d_in[3];
    const float* wavemat = (const float*)d_in[4];
    float* out = (float*)d_out;

    cudaFuncSetAttribute(zoe_all, cudaFuncAttributeMaxDynamicSharedMemorySize,
                         SMEM_BYTES);

    zoe_all<<<NBLK, 256, SMEM_BYTES>>>(vp, vs, rho, theta, wavemat, out);
}

// round 15
// speedup vs baseline: 1.9796x; 1.9796x over previous
#include <cuda_runtime.h>
#include <cuda_fp16.h>
#include <math.h>
#include <stdint.h>

#define L_LAYERS 250
#define N_TRACES 600
#define N_THETA  30
#define NI   249                 // interfaces (ref row 249 is zero -> dropped)
#define NCOL 18000               // N_TRACES * N_THETA
#define NP   18048               // padded R plane pitch (cols)
#define KPAD 256                 // padded K
#define TOTAL (NI * NCOL)
#define HTOTAL (TOTAL / 2)       // angle-pair count
#define WELEMS (256 * 256)
#define NTIL 282                 // n-tiles of 64 (18048)

// fp16 planes. __device__ globals are zero-initialized at module load.
// Pad regions (R rows >= 249, cols >= 18000) are NEVER written by any
// kernel, so they remain zero across all graph replays.
// g_Wp is W packed with a k-permutation making HMMA A-fragments
// 8-byte-contiguous: within each 16-k group, position(k) =
// ((k&6)<<1) | ((k&8)>>2) | (k&1).
__device__ __half g_Rh[KPAD * NP];
__device__ __half g_Wp[256 * 256];

__device__ __forceinline__ float sqrt_approx(float x) {
    float r;
    asm("sqrt.approx.f32 %0, %1;" : "=f"(r) : "f"(x));
    return r;
}

// ---------------------------------------------------------------------------
// Phase 1 (round-8 proven, byte-identical numerics): exact Zoeppritz Rpp via
// the Aki & Richards closed form, rescaled by a1*a2*b1*b2. One thread does
// TWO adjacent angles -> __half2 store. Tail blocks pack W (fp32 -> fp16,
// k-permuted fragment-linear layout).
// ---------------------------------------------------------------------------
__global__ void zoe_phase1(const float* __restrict__ vp,
                           const float* __restrict__ vs,
                           const float* __restrict__ rho,
                           const float* __restrict__ theta,
                           const float* __restrict__ W) {
    int gidx = blockIdx.x * 256 + threadIdx.x;

    if (gidx >= HTOTAL) {
        int idx = gidx - HTOTAL;
        if (idx < WELEMS) {
            int r = idx >> 8, k = idx & 255;
            float v = (r < L_LAYERS && k < L_LAYERS) ? W[r * L_LAYERS + k] : 0.f;
            int p16 = ((k & 6) << 1) | ((k & 8) >> 2) | (k & 1);
            int kpos = (k & 240) | p16;
            g_Wp[r * 256 + kpos] = __float2half(v);
        }
        return;
    }

    __shared__ float s_sth[N_THETA], s_cth[N_THETA];
    int tid = threadIdx.x;
    if (tid < N_THETA) {
        float sv, cv;
        sincosf(theta[tid], &sv, &cv);
        s_sth[tid] = sv;
        s_cth[tid] = cv;
    }
    __syncthreads();

    int l   = gidx / (NCOL / 2);
    int rem = gidx - l * (NCOL / 2);
    int t   = rem / (N_THETA / 2);
    int ap  = rem - t * (N_THETA / 2);
    int a0  = ap * 2;
    int n   = t * N_THETA + a0;

    float a1 = vp[l * N_TRACES + t],  a2 = vp[(l + 1) * N_TRACES + t];
    float b1 = vs[l * N_TRACES + t],  b2 = vs[(l + 1) * N_TRACES + t];
    float r1 = rho[l * N_TRACES + t], r2 = rho[(l + 1) * N_TRACES + t];

    float inva1 = __fdividef(1.f, a1);
    float k1 = 2.f * r1 * (b1 * b1);
    float k2 = 2.f * r2 * (b2 * b2);
    float d  = k2 - k1;
    float drho = r2 - r1;
    float a1b2 = a1 * b2;
    float a2b1 = a2 * b1;

    float rv[2];
#pragma unroll
    for (int j = 0; j < 2; j++) {
        float sth = s_sth[a0 + j], cth = s_cth[a0 + j];
        float p  = sth * inva1;
        float p2 = p * p;

        float st2 = p * a2;
        float ct2 = sqrt_approx(fmaxf(1.f - st2 * st2, 0.f));
        float sp1 = p * b1;
        float cp1 = sqrt_approx(fmaxf(1.f - sp1 * sp1, 0.f));
        float sp2 = p * b2;
        float cp2 = sqrt_approx(fmaxf(1.f - sp2 * sp2, 0.f));

        float dp2 = d * p2;
        float A = drho - dp2;
        float B = r2 - dp2;
        float C = r1 + dp2;

        float X = B * cth * a2;
        float Y = C * ct2 * a1;
        float E = X + Y;
        float F = fmaf(B * cp1, b2, C * cp2 * b1);
        float Z = d * cth * cp2;
        float Aa1b2 = A * a1b2;
        float G = Aa1b2 - Z;
        float H = fmaf(-d * ct2, cp1, A * a2b1);
        float D = fmaf(E, F, G * H * p2);
        float num = fmaf(X - Y, F, -(Aa1b2 + Z) * H * p2);

        rv[j] = __fdividef(num, D);
    }

    size_t o = ((size_t)l * NP + n) >> 1;
    reinterpret_cast<__half2*>(g_Rh)[o] =
        __halves2half2(__float2half(rv[0]), __float2half(rv[1]));
}

// ---------------------------------------------------------------------------
// Phase 2: out[t, l, a] = sum_k W[l, k] * R[k, n], n = t*30 + a
// Pure-fp16 HMMA GEMM, barrier-minimal:
//   Block = 256(M) x 64(N), 256 threads, 8 warps of 32m x 64n (mt=2, nt=8).
//   B tile (256k x 64n, 36 KB STATIC smem): one cp.async burst, one wait,
//   ONE __syncthreads, then 16 fully-unrolled k-steps with NO barriers.
//   A fragments loaded directly from L2-hot k-permuted g_Wp via LDG.64
//   (no A smem, no ldsm for A).
// Grid = 282 blocks (one per 64-wide n-tile) ~= one wave at 2 blocks/SM.
// ---------------------------------------------------------------------------
#define BPITCH 72                    // 64 + 8 pad halves (144B rows)

__device__ __forceinline__ uint32_t smaddr(const void* p) {
    return (uint32_t)__cvta_generic_to_shared(p);
}
__device__ __forceinline__ void ldsm4t(uint32_t a[4], uint32_t addr) {
    asm volatile("ldmatrix.sync.aligned.m8n8.x4.trans.shared.b16 {%0,%1,%2,%3}, [%4];"
                 : "=r"(a[0]), "=r"(a[1]), "=r"(a[2]), "=r"(a[3]) : "r"(addr));
}
__device__ __forceinline__ void mma16816(float c[4], const uint32_t a[4], const uint32_t b[2]) {
    asm volatile("mma.sync.aligned.m16n8k16.row.col.f32.f16.f16.f32 "
                 "{%0,%1,%2,%3}, {%4,%5,%6,%7}, {%8,%9}, {%0,%1,%2,%3};"
                 : "+f"(c[0]), "+f"(c[1]), "+f"(c[2]), "+f"(c[3])
                 : "r"(a[0]), "r"(a[1]), "r"(a[2]), "r"(a[3]), "r"(b[0]), "r"(b[1]));
}
#define CP16(dst, src) \
    asm volatile("cp.async.ca.shared.global [%0], [%1], 16;" :: "r"(dst), "l"(src))
#define CP_COMMIT() asm volatile("cp.async.commit_group;")
#define CP_WAIT0()  asm volatile("cp.async.wait_group 0;")

__global__ __launch_bounds__(256, 2)
void zoe_gemm(float* __restrict__ out) {
    __shared__ __half Bs[256][BPITCH];

    int tid = threadIdx.x;
    int bn = blockIdx.x * 64;

    // ---- B fill: row k = tid, 8 CP16 (64 halves = 128 B) ----
    {
        const __half* src = &g_Rh[(size_t)tid * NP + bn];
        uint32_t dst = smaddr(&Bs[tid][0]);
#pragma unroll
        for (int c = 0; c < 8; c++)
            CP16(dst + c * 16, src + c * 8);
        CP_COMMIT();
    }

    // ---- warp mapping: 8 warps x 32m, full 64n per warp ----
    int wid = tid >> 5, lane = tid & 31;
    int wm = wid * 32;
    int g = lane >> 2, tg = lane & 3;
    int r8 = lane >> 3, i8 = lane & 7;
    int b_fkrow = (r8 & 1) * 8 + i8;           // + ks*16
    int b_fncol = (r8 >> 1) * 8;               // + pair*16

    // A fragment pointers (k-permuted layout: lane fragment = 4 contiguous
    // halves at kpos = ks*16 + tg*4; rows g and g+8 of the 16m tile)
    const __half* pA0 = &g_Wp[(wm + g) * 256 + tg * 4];
    const __half* pA1 = pA0 + 8 * 256;

    uint32_t sBf = smaddr(&Bs[b_fkrow][b_fncol]);

    float acc[2][8][4];
#pragma unroll
    for (int mt = 0; mt < 2; mt++)
#pragma unroll
        for (int nt = 0; nt < 8; nt++)
#pragma unroll
            for (int e = 0; e < 4; e++) acc[mt][nt][e] = 0.f;

    CP_WAIT0();
    __syncthreads();                           // the ONLY barrier

    // ---- 16 k-steps, fully unrolled, barrier-free ----
#pragma unroll
    for (int ks = 0; ks < 16; ks++) {
        uint32_t bhf[8][2];
#pragma unroll
        for (int pair = 0; pair < 4; pair++) {
            uint32_t t4[4];
            ldsm4t(t4, sBf + ks * 16 * (BPITCH * 2) + pair * 32);
            bhf[pair * 2][0] = t4[0]; bhf[pair * 2][1] = t4[1];
            bhf[pair * 2 + 1][0] = t4[2]; bhf[pair * 2 + 1][1] = t4[3];
        }
#pragma unroll
        for (int mt = 0; mt < 2; mt++) {
            uint2 a02 = *(const uint2*)(pA0 + mt * 16 * 256 + ks * 16);
            uint2 a13 = *(const uint2*)(pA1 + mt * 16 * 256 + ks * 16);
            uint32_t ahf[4] = {a02.x, a13.x, a02.y, a13.y};
#pragma unroll
            for (int nt = 0; nt < 8; nt++) {
                mma16816(acc[mt][nt], ahf, bhf[nt]);
            }
        }
    }

    // ---- epilogue ----
#pragma unroll
    for (int mt = 0; mt < 2; mt++) {
#pragma unroll
        for (int nt = 0; nt < 8; nt++) {
            int l0 = wm + mt * 16 + (lane >> 2);
            int n0 = bn + nt * 8 + (lane & 3) * 2;
#pragma unroll
            for (int e = 0; e < 4; e++) {
                int l = l0 + (e >> 1) * 8;
                int n = n0 + (e & 1);
                if (l < L_LAYERS && n < NCOL) {
                    int t = n / N_THETA;
                    int a = n - t * N_THETA;
                    out[t * (L_LAYERS * N_THETA) + l * N_THETA + a] = acc[mt][nt][e];
                }
            }
        }
    }
}

extern "C" void kernel_launch(void* const* d_in, const int* in_sizes, int n_in,
                              void* d_out, int out_size) {
    const float* vp      = (const float*)d_in[0];
    const float* vs      = (const float*)d_in[1];
    const float* rho     = (const float*)d_in[2];
    const float* theta   = (const float*)d_in[3];
    const float* wavemat = (const float*)d_in[4];
    float* out = (float*)d_out;

    int nblk = (HTOTAL + WELEMS + 255) / 256;
    zoe_phase1<<<nblk, 256>>>(vp, vs, rho, theta, wavemat);

    zoe_gemm<<<NTIL, 256>>>(out);
}

// round 16
// speedup vs baseline: 2.0936x; 1.0576x over previous
#include <cuda_runtime.h>
#include <cuda_fp16.h>
#include <math.h>
#include <stdint.h>

#define L_LAYERS 250
#define N_TRACES 600
#define N_THETA  30
#define NI   249                 // interfaces (ref row 249 is zero -> dropped)
#define NCOL 18000               // N_TRACES * N_THETA
#define NP   18048               // padded R plane pitch (cols)
#define KPAD 256                 // padded K
#define TOTAL (NI * NCOL)
#define HTOTAL (TOTAL / 2)       // angle-pair count
#define WELEMS (256 * 256)

// fp16 planes. __device__ globals are zero-initialized at module load.
// Pad regions (rows >= 249, cols >= 18000) are NEVER written by any kernel,
// so they remain zero across all graph replays.
__device__ __half g_Rh[KPAD * NP];
__device__ __half g_Wh[256 * 256];

__device__ __forceinline__ float sqrt_approx(float x) {
    float r;
    asm("sqrt.approx.f32 %0, %1;" : "=f"(r) : "f"(x));
    return r;
}

// ---- packed f32x2 helpers (sm_100+ base ISA) ----
typedef unsigned long long u64t;
__device__ __forceinline__ u64t pk2(float a, float b) {
    u64t r; asm("mov.b64 %0, {%1, %2};" : "=l"(r) : "f"(a), "f"(b)); return r;
}
__device__ __forceinline__ u64t bc2(float a) { return pk2(a, a); }
__device__ __forceinline__ void up2(u64t v, float& a, float& b) {
    asm("mov.b64 {%0, %1}, %2;" : "=f"(a), "=f"(b) : "l"(v));
}
__device__ __forceinline__ u64t mul2(u64t a, u64t b) {
    u64t d; asm("mul.rn.f32x2 %0, %1, %2;" : "=l"(d) : "l"(a), "l"(b)); return d;
}
__device__ __forceinline__ u64t add2(u64t a, u64t b) {
    u64t d; asm("add.rn.f32x2 %0, %1, %2;" : "=l"(d) : "l"(a), "l"(b)); return d;
}
__device__ __forceinline__ u64t fma2(u64t a, u64t b, u64t c) {
    u64t d; asm("fma.rn.f32x2 %0, %1, %2, %3;" : "=l"(d) : "l"(a), "l"(b), "l"(c)); return d;
}
__device__ __forceinline__ u64t neg2(u64t a) { return a ^ 0x8000000080000000ULL; }
__device__ __forceinline__ u64t sqrt2c(u64t a) {
    float x, y; up2(a, x, y);
    x = sqrt_approx(fmaxf(x, 0.f));
    y = sqrt_approx(fmaxf(y, 0.f));
    return pk2(x, y);
}

// ---------------------------------------------------------------------------
// Phase 1 (fused): exact Zoeppritz Rpp via the Aki & Richards closed form,
// rescaled by a1*a2*b1*b2. One thread computes TWO adjacent angles, packed
// into f32x2 lanes (identical per-lane arithmetic to the proven scalar
// version). Clipping never activates for these input ranges (p*a2 <= 0.836).
// Blocks past the pair range convert W fp32 -> fp16.
// ---------------------------------------------------------------------------
__global__ void zoe_phase1(const float* __restrict__ vp,
                           const float* __restrict__ vs,
                           const float* __restrict__ rho,
                           const float* __restrict__ theta,
                           const float* __restrict__ W) {
    int gidx = blockIdx.x * 256 + threadIdx.x;

    if (gidx >= HTOTAL) {
        int idx = gidx - HTOTAL;
        if (idx < WELEMS) {
            int r = idx >> 8, k = idx & 255;
            float v = (r < L_LAYERS && k < L_LAYERS) ? W[r * L_LAYERS + k] : 0.f;
            g_Wh[idx] = __float2half(v);
        }
        return;
    }

    __shared__ float s_sth[N_THETA], s_cth[N_THETA];
    int tid = threadIdx.x;
    if (tid < N_THETA) {
        float sv, cv;
        sincosf(theta[tid], &sv, &cv);
        s_sth[tid] = sv;
        s_cth[tid] = cv;
    }
    __syncthreads();

    int l   = gidx / (NCOL / 2);
    int rem = gidx - l * (NCOL / 2);
    int t   = rem / (N_THETA / 2);
    int ap  = rem - t * (N_THETA / 2);
    int a0  = ap * 2;
    int n   = t * N_THETA + a0;

    float a1 = vp[l * N_TRACES + t],  a2 = vp[(l + 1) * N_TRACES + t];
    float b1 = vs[l * N_TRACES + t],  b2 = vs[(l + 1) * N_TRACES + t];
    float r1 = rho[l * N_TRACES + t], r2 = rho[(l + 1) * N_TRACES + t];

    float inva1 = __fdividef(1.f, a1);
    float dsc  = 2.f * r2 * (b2 * b2) - 2.f * r1 * (b1 * b1);

    // broadcast constants
    u64t vInva1 = bc2(inva1);
    u64t vA1 = bc2(a1),   vA2 = bc2(a2);
    u64t vB1 = bc2(b1),   vB2 = bc2(b2);
    u64t vR1 = bc2(r1),   vR2 = bc2(r2);
    u64t vD  = bc2(dsc);
    u64t vDrho = bc2(r2 - r1);
    u64t vA1B2 = bc2(a1 * b2);
    u64t vA2B1 = bc2(a2 * b1);
    u64t vOne = bc2(1.f);

    // packed angle pair
    u64t sth = pk2(s_sth[a0], s_sth[a0 + 1]);
    u64t cth = pk2(s_cth[a0], s_cth[a0 + 1]);

    u64t p  = mul2(sth, vInva1);
    u64t p2 = mul2(p, p);

    u64t st2 = mul2(p, vA2);
    u64t ct2 = sqrt2c(fma2(neg2(st2), st2, vOne));
    u64t sp1 = mul2(p, vB1);
    u64t cp1 = sqrt2c(fma2(neg2(sp1), sp1, vOne));
    u64t sp2 = mul2(p, vB2);
    u64t cp2 = sqrt2c(fma2(neg2(sp2), sp2, vOne));

    u64t dp2 = mul2(vD, p2);
    u64t A = add2(vDrho, neg2(dp2));
    u64t B = add2(vR2, neg2(dp2));
    u64t C = add2(vR1, dp2);

    u64t X = mul2(mul2(B, cth), vA2);
    u64t Y = mul2(mul2(C, ct2), vA1);
    u64t E = add2(X, Y);
    u64t F = fma2(mul2(B, cp1), vB2, mul2(mul2(C, cp2), vB1));
    u64t Z = mul2(mul2(vD, cth), cp2);
    u64t Aa1b2 = mul2(A, vA1B2);
    u64t G = add2(Aa1b2, neg2(Z));
    u64t H = fma2(neg2(mul2(vD, ct2)), cp1, mul2(A, vA2B1));
    u64t Dd = fma2(E, F, mul2(mul2(G, H), p2));
    u64t num = fma2(add2(X, neg2(Y)), F, neg2(mul2(mul2(add2(Aa1b2, Z), H), p2)));

    float n0f, n1f, d0f, d1f;
    up2(num, n0f, n1f);
    up2(Dd, d0f, d1f);
    float rv0 = __fdividef(n0f, d0f);
    float rv1 = __fdividef(n1f, d1f);

    size_t o = ((size_t)l * NP + n) >> 1;
    reinterpret_cast<__half2*>(g_Rh)[o] =
        __halves2half2(__float2half(rv0), __float2half(rv1));
}

// ---------------------------------------------------------------------------
// Phase 2: out[t, l, a] = sum_k W[l, k] * R[k, n], n = t*30 + a
// Pure-fp16 HMMA GEMM: acc += Wh*Rh (fp32 accumulate).
// M=256, N=18000(pad 18048), K=256. Block 128x128, 8 warps (2x4),
// warp 64x32, m16n8k16. 4-stage cp.async pipeline, fully unrolled,
// one __syncthreads per k-step, prefetch distance 3.
// (round-8 measured configuration, byte-exact)
// ---------------------------------------------------------------------------
#define APITCH 24
#define BPITCH 136
#define ASTG (128 * APITCH)          // halves per A stage: 3072
#define BSTG (16 * BPITCH)           // halves per B stage: 2176
#define SMEM_BYTES ((4 * ASTG + 4 * BSTG) * 2)   // 41984

__device__ __forceinline__ uint32_t smaddr(const void* p) {
    return (uint32_t)__cvta_generic_to_shared(p);
}
__device__ __forceinline__ void ldsm4(uint32_t a[4], uint32_t addr) {
    asm volatile("ldmatrix.sync.aligned.m8n8.x4.shared.b16 {%0,%1,%2,%3}, [%4];"
                 : "=r"(a[0]), "=r"(a[1]), "=r"(a[2]), "=r"(a[3]) : "r"(addr));
}
__device__ __forceinline__ void ldsm4t(uint32_t a[4], uint32_t addr) {
    asm volatile("ldmatrix.sync.aligned.m8n8.x4.trans.shared.b16 {%0,%1,%2,%3}, [%4];"
                 : "=r"(a[0]), "=r"(a[1]), "=r"(a[2]), "=r"(a[3]) : "r"(addr));
}
__device__ __forceinline__ void mma16816(float c[4], const uint32_t a[4], const uint32_t b[2]) {
    asm volatile("mma.sync.aligned.m16n8k16.row.col.f32.f16.f16.f32 "
                 "{%0,%1,%2,%3}, {%4,%5,%6,%7}, {%8,%9}, {%0,%1,%2,%3};"
                 : "+f"(c[0]), "+f"(c[1]), "+f"(c[2]), "+f"(c[3])
                 : "r"(a[0]), "r"(a[1]), "r"(a[2]), "r"(a[3]), "r"(b[0]), "r"(b[1]));
}
#define CP16(dst, src) \
    asm volatile("cp.async.ca.shared.global [%0], [%1], 16;" :: "r"(dst), "l"(src))
#define CP_COMMIT() asm volatile("cp.async.commit_group;")
#define CP_WAIT(n)  asm volatile("cp.async.wait_group %0;" :: "n"(n))

__global__ __launch_bounds__(256, 2)
void zoe_gemm(float* __restrict__ out) {
    extern __shared__ __half sm[];
    __half* Ah = sm;                      // 4 * ASTG halves
    __half* Bh = sm + 4 * ASTG;           // 4 * BSTG halves

    int tid = threadIdx.x;
    int bm = blockIdx.y * 128;
    int bn = blockIdx.x * 128;

    int ar = tid >> 1;
    int ac = (tid & 1) * 8;
    int br = tid >> 4;
    int bc = (tid & 15) * 8;

    const __half* pWh = &g_Wh[(bm + ar) * 256 + ac];
    const __half* pRh = &g_Rh[(size_t)br * NP + bn + bc];

    uint32_t sA = smaddr(&Ah[ar * APITCH + ac]);
    uint32_t sB = smaddr(&Bh[br * BPITCH + bc]);

    int wid = tid >> 5, lane = tid & 31;
    int wm = (wid >> 2) * 64;
    int wn = (wid & 3) * 32;
    int r8 = lane >> 3, i8 = lane & 7;
    int a_row = wm + (r8 & 1) * 8 + i8;
    int a_col = (r8 >> 1) * 8;
    int b_krow = (r8 & 1) * 8 + i8;
    int b_ncol = wn + (r8 >> 1) * 8;

    uint32_t sAf = smaddr(&Ah[a_row * APITCH + a_col]);
    uint32_t sBf = smaddr(&Bh[b_krow * BPITCH + b_ncol]);

    float acc[4][4][4];
#pragma unroll
    for (int mt = 0; mt < 4; mt++)
#pragma unroll
        for (int nt = 0; nt < 4; nt++)
#pragma unroll
            for (int e = 0; e < 4; e++) acc[mt][nt][e] = 0.f;

    const int NSTEP = KPAD / 16;  // 16

    // prologue: stages 0..2
#pragma unroll
    for (int s = 0; s < 3; s++) {
        int k0 = s * 16;
        CP16(sA + s * (ASTG * 2), pWh + k0);
        CP16(sB + s * (BSTG * 2), pRh + (size_t)k0 * NP);
        CP_COMMIT();
    }

#pragma unroll
    for (int s = 0; s < NSTEP; s++) {
        if (s <= NSTEP - 3) { CP_WAIT(2); }
        else if (s == NSTEP - 2) { CP_WAIT(1); }
        else { CP_WAIT(0); }
        __syncthreads();   // also proves step s-1 readers of buffer (s+3)&3 done

        if (s + 3 < NSTEP) {
            int k0 = (s + 3) * 16;
            int nb = (s + 3) & 3;
            CP16(sA + nb * (ASTG * 2), pWh + k0);
            CP16(sB + nb * (BSTG * 2), pRh + (size_t)k0 * NP);
            CP_COMMIT();
        }

        int buf = s & 3;
        uint32_t aBase = sAf + buf * (ASTG * 2);
        uint32_t bBase = sBf + buf * (BSTG * 2);

        uint32_t bhf[4][2];
#pragma unroll
        for (int pair = 0; pair < 2; pair++) {
            uint32_t t4[4];
            ldsm4t(t4, bBase + pair * 32);
            bhf[pair * 2][0] = t4[0]; bhf[pair * 2][1] = t4[1];
            bhf[pair * 2 + 1][0] = t4[2]; bhf[pair * 2 + 1][1] = t4[3];
        }

#pragma unroll
        for (int mt = 0; mt < 4; mt++) {
            uint32_t ahf[4];
            ldsm4(ahf, aBase + mt * 16 * (APITCH * 2));
#pragma unroll
            for (int nt = 0; nt < 4; nt++) {
                mma16816(acc[mt][nt], ahf, bhf[nt]);
            }
        }
    }

    // epilogue
#pragma unroll
    for (int mt = 0; mt < 4; mt++) {
#pragma unroll
        for (int nt = 0; nt < 4; nt++) {
            int l0 = bm + wm + mt * 16 + (lane >> 2);
            int n0 = bn + wn + nt * 8 + (lane & 3) * 2;
#pragma unroll
            for (int e = 0; e < 4; e++) {
                int l = l0 + (e >> 1) * 8;
                int n = n0 + (e & 1);
                if (l < L_LAYERS && n < NCOL) {
                    int t = n / N_THETA;
                    int a = n - t * N_THETA;
                    out[t * (L_LAYERS * N_THETA) + l * N_THETA + a] = acc[mt][nt][e];
                }
            }
        }
    }
}

extern "C" void kernel_launch(void* const* d_in, const int* in_sizes, int n_in,
                              void* d_out, int out_size) {
    const float* vp      = (const float*)d_in[0];
    const float* vs      = (const float*)d_in[1];
    const float* rho     = (const float*)d_in[2];
    const float* theta   = (const float*)d_in[3];
    const float* wavemat = (const float*)d_in[4];
    float* out = (float*)d_out;

    cudaFuncSetAttribute(zoe_gemm, cudaFuncAttributeMaxDynamicSharedMemorySize,
                         SMEM_BYTES);

    int nblk = (HTOTAL + WELEMS + 255) / 256;
    zoe_phase1<<<nblk, 256>>>(vp, vs, rho, theta, wavemat);

    dim3 grid((NCOL + 127) / 128, 2);
    zoe_gemm<<<grid, 256, SMEM_BYTES>>>(out);
}